// round 2
// baseline (speedup 1.0000x reference)
#include <cuda_runtime.h>
#include <math.h>

#define IN_DIM   256
#define OUT_DIM  512
#define MEM_LEN  131072
#define BETA_F   1.0f

// scratch (no device allocs allowed -> __device__ globals)
__device__ float        g_partial[4 * OUT_DIM];
__device__ float        g_enc[OUT_DIM];
__device__ unsigned int g_minbits;

// ---------------------------------------------------------------------------
// Kernel 1a: normalize x, partial matvec (k-split over 4 blocks). Also resets
// the global min for this launch (graph replay safe).
// ---------------------------------------------------------------------------
__global__ void __launch_bounds__(512) k_enc_partial(
    const float* __restrict__ x, const float* __restrict__ W,
    const float* __restrict__ mean, const float* __restrict__ stdv)
{
    __shared__ float xn[IN_DIM];
    int tid = threadIdx.x;
    if (tid < IN_DIM) {
        float s = stdv[tid];
        xn[tid] = (s == 0.0f) ? 0.0f : (x[tid] - mean[tid]) / s;
    }
    if (blockIdx.x == 0 && tid == 0) g_minbits = 0x7F800000u;  // +inf
    __syncthreads();

    const int KB = IN_DIM / 4;           // 64 k's per block
    int k0 = blockIdx.x * KB;
    float acc = 0.0f;
#pragma unroll 16
    for (int k = 0; k < KB; k++)
        acc = fmaf(xn[k0 + k], W[(k0 + k) * OUT_DIM + tid], acc);
    g_partial[blockIdx.x * OUT_DIM + tid] = acc;
}

// ---------------------------------------------------------------------------
// Kernel 1b: combine partials + bias, log_softmax over 512 logits -> g_enc
// ---------------------------------------------------------------------------
__global__ void __launch_bounds__(512) k_softmax(const float* __restrict__ b_enc)
{
    int tid  = threadIdx.x;
    int lane = tid & 31, warp = tid >> 5;     // 16 warps
    __shared__ float sred[16];

    float logit = g_partial[tid] + g_partial[OUT_DIM + tid] +
                  g_partial[2 * OUT_DIM + tid] + g_partial[3 * OUT_DIM + tid] +
                  b_enc[tid];

    // block max
    float m = logit;
#pragma unroll
    for (int o = 16; o; o >>= 1) m = fmaxf(m, __shfl_xor_sync(0xffffffffu, m, o));
    if (lane == 0) sred[warp] = m;
    __syncthreads();
    m = sred[0];
#pragma unroll
    for (int i = 1; i < 16; i++) m = fmaxf(m, sred[i]);
    __syncthreads();

    // block sum of exp
    float e = expf(logit - m);
    float s = e;
#pragma unroll
    for (int o = 16; o; o >>= 1) s += __shfl_xor_sync(0xffffffffu, s, o);
    if (lane == 0) sred[warp] = s;
    __syncthreads();
    s = 0.0f;
#pragma unroll
    for (int i = 0; i < 16; i++) s += sred[i];

    g_enc[tid] = logit - m - logf(s);
}

// ---------------------------------------------------------------------------
// Kernel 2: fused memory copy (shifted +1 into output) + L1 distance + min.
// 256 threads = 2 rows (512 floats = 128 float4) per iteration.
// grid 8192, 8 iterations each -> exactly covers 65536 row-pairs.
// ---------------------------------------------------------------------------
__global__ void __launch_bounds__(256) k_mem(
    const float* __restrict__ mem, float* __restrict__ O)
{
    __shared__ float enc_s[OUT_DIM];
    __shared__ float wsum[8];
    int tid  = threadIdx.x;
    int lane = tid & 31;

    enc_s[tid]       = g_enc[tid];
    enc_s[tid + 256] = g_enc[tid + 256];
    __syncthreads();

    const float4* mem4 = (const float4*)mem;
    float4*       O4   = (float4*)O;           // O[0] is loss slot; O4[i] = O[4i..4i+3]
    const float4* e4p  = (const float4*)enc_s;
    const float4  e    = e4p[tid & 127];

    const int NPAIR = MEM_LEN / 2;              // 65536
    const int LAST4 = MEM_LEN * (OUT_DIM / 4) - 1;  // 16777215
    float localmin = __int_as_float(0x7f800000);

    for (int p = blockIdx.x; p < NPAIR; p += gridDim.x) {
        int i4 = p * 256 + tid;                 // float4 index into memory
        float4 v = mem4[i4];

        float d = fabsf(v.x - e.x) + fabsf(v.y - e.y) +
                  fabsf(v.z - e.z) + fabsf(v.w - e.w);

        // ---- shifted aligned store: O[1 + 4*i4 + j] = memory[4*i4 + j]
        float wprev = __shfl_up_sync(0xffffffffu, v.w, 1);
        if (lane == 0 && i4 > 0) wprev = __ldg(&mem[4 * i4 - 1]);
        if (i4 > 0) {
            O4[i4] = make_float4(wprev, v.x, v.y, v.z);
        } else {
            O[1] = v.x; O[2] = v.y; O[3] = v.z;
        }
        if (i4 == LAST4) O[4 * i4 + 4] = v.w;   // final memory element

        // ---- per-row L1 sums: warps 0-3 = row A, warps 4-7 = row B
#pragma unroll
        for (int o = 16; o; o >>= 1) d += __shfl_xor_sync(0xffffffffu, d, o);
        if (lane == 0) wsum[tid >> 5] = d;
        __syncthreads();
        if (tid == 0) {
            float rA = wsum[0] + wsum[1] + wsum[2] + wsum[3];
            float rB = wsum[4] + wsum[5] + wsum[6] + wsum[7];
            localmin = fminf(localmin, fminf(rA, rB));
        }
        __syncthreads();
    }
    if (tid == 0)
        atomicMin(&g_minbits, __float_as_uint(localmin));   // dists >= 0: uint order == float order
}

// ---------------------------------------------------------------------------
// Kernel 3: mem_data shifted copy. Output region starts at O[1 + 64M] (== 1 mod 4).
// ---------------------------------------------------------------------------
__global__ void __launch_bounds__(256) k_memdata(
    const float* __restrict__ md, float* __restrict__ O)
{
    const int  N4   = MEM_LEN * (IN_DIM / 4);          // 8388608 float4s
    const int  OB4  = MEM_LEN * (OUT_DIM / 4);          // 16777216: float4 offset of mem_data region - shift
    const long long base = 1LL + (long long)MEM_LEN * OUT_DIM;  // 67108865

    const float4* md4 = (const float4*)md;
    float4*       O4  = (float4*)O;
    int lane = threadIdx.x & 31;

    for (int j4 = blockIdx.x * blockDim.x + threadIdx.x; j4 < N4;
         j4 += gridDim.x * blockDim.x) {
        float4 v = md4[j4];
        float wprev = __shfl_up_sync(0xffffffffu, v.w, 1);
        if (lane == 0 && j4 > 0) wprev = __ldg(&md[4 * j4 - 1]);
        if (j4 > 0) {
            O4[OB4 + j4] = make_float4(wprev, v.x, v.y, v.z);  // O[base-1+4j4 .. +3] = md[4j4-1 .. 4j4+2]
        } else {
            O[base] = v.x; O[base + 1] = v.y; O[base + 2] = v.z;
        }
        if (j4 == N4 - 1) O[base + 4LL * N4 - 1] = v.w;        // final element
    }
}

// ---------------------------------------------------------------------------
// Kernel 4: write loss; conditional ring-buffer row overwrite in the OUTPUT.
// ---------------------------------------------------------------------------
__global__ void __launch_bounds__(512) k_final(
    const float* __restrict__ x, const int* __restrict__ count,
    float* __restrict__ O)
{
    int tid = threadIdx.x;
    float loss = __uint_as_float(g_minbits);
    if (tid == 0) O[0] = loss;
    if (loss <= BETA_F) {
        int pos = count[0] % MEM_LEN;
        O[1LL + (long long)pos * OUT_DIM + tid] = g_enc[tid];
        if (tid < IN_DIM)
            O[1LL + (long long)MEM_LEN * OUT_DIM + (long long)pos * IN_DIM + tid] = x[tid];
    }
}

// ---------------------------------------------------------------------------
extern "C" void kernel_launch(void* const* d_in, const int* in_sizes, int n_in,
                              void* d_out, int out_size)
{
    const float* x        = (const float*)d_in[0];
    const float* W_enc    = (const float*)d_in[1];
    const float* b_enc    = (const float*)d_in[2];
    const float* memory   = (const float*)d_in[3];
    const float* mem_data = (const float*)d_in[4];
    const float* mean     = (const float*)d_in[5];
    const float* stdv     = (const float*)d_in[6];
    const int*   count    = (const int*)d_in[n_in - 1];   // scalar count (last input)
    float* O = (float*)d_out;

    k_enc_partial<<<4, 512>>>(x, W_enc, mean, stdv);
    k_softmax<<<1, 512>>>(b_enc);
    k_mem<<<8192, 256>>>(memory, O);
    k_memdata<<<4096, 256>>>(mem_data, O);
    k_final<<<1, 512>>>(x, count, O);
}

// round 3
// speedup vs baseline: 1.0531x; 1.0531x over previous
#include <cuda_runtime.h>
#include <math.h>

#define IN_DIM   256
#define OUT_DIM  512
#define MEM_LEN  131072
#define BETA_F   1.0f

#define NB_MEM   4096     // blocks for memory stream (512 MB of traffic)
#define NB_MD    2048     // blocks for mem_data stream (256 MB of traffic)

// scratch (no device allocs allowed -> __device__ globals)
__device__ float        g_enc[OUT_DIM];
__device__ unsigned int g_minbits;

// ---------------------------------------------------------------------------
// Kernel 1: fused encoder. 1 block x 1024 threads, 2-way k-split matvec,
// smem combine, block log_softmax. Also resets the global min (replay-safe).
// ---------------------------------------------------------------------------
__global__ void __launch_bounds__(1024) k_encoder(
    const float* __restrict__ x, const float* __restrict__ W,
    const float* __restrict__ b_enc, const float* __restrict__ mean,
    const float* __restrict__ stdv)
{
    __shared__ float xn[IN_DIM];
    __shared__ float part[1024];
    __shared__ float sred[16];
    int tid = threadIdx.x;

    if (tid < IN_DIM) {
        float s = stdv[tid];
        xn[tid] = (s == 0.0f) ? 0.0f : (x[tid] - mean[tid]) / s;
    }
    if (tid == 0) g_minbits = 0x7F800000u;   // +inf
    __syncthreads();

    int col = tid & 511;
    int ks  = tid >> 9;                       // 0 or 1: k-halves
    const float* Wp = W + (ks * 128) * OUT_DIM + col;
    float acc = 0.0f;
#pragma unroll 8
    for (int k = 0; k < 128; k++)
        acc = fmaf(xn[ks * 128 + k], Wp[k * OUT_DIM], acc);
    part[tid] = acc;
    __syncthreads();

    int lane = tid & 31, warp = tid >> 5;
    float logit = 0.0f;
    if (tid < OUT_DIM) logit = part[tid] + part[tid + 512] + b_enc[tid];

    // block max over first 512 threads
    float m = (tid < OUT_DIM) ? logit : -INFINITY;
#pragma unroll
    for (int o = 16; o; o >>= 1) m = fmaxf(m, __shfl_xor_sync(0xffffffffu, m, o));
    if (lane == 0 && warp < 16) sred[warp] = m;
    __syncthreads();
    m = sred[0];
#pragma unroll
    for (int i = 1; i < 16; i++) m = fmaxf(m, sred[i]);
    __syncthreads();

    // block sum of exp
    float e = (tid < OUT_DIM) ? expf(logit - m) : 0.0f;
    float s = e;
#pragma unroll
    for (int o = 16; o; o >>= 1) s += __shfl_xor_sync(0xffffffffu, s, o);
    if (lane == 0 && warp < 16) sred[warp] = s;
    __syncthreads();

    if (tid < OUT_DIM) {
        s = 0.0f;
#pragma unroll
        for (int i = 0; i < 16; i++) s += sred[i];
        g_enc[tid] = logit - m - logf(s);
    }
}

// ---------------------------------------------------------------------------
// Kernel 2: fused big streamer.
//   blocks [0, NB_MEM):      memory -> O (shifted +1) + L1 distance + min
//                            warp-per-row, 4 rows per warp, no hot barriers
//   blocks [NB_MEM, +NB_MD): mem_data -> O (shifted +1)
// Shift handled with aligned float4 loads/stores + shuffle carry chain.
// ---------------------------------------------------------------------------
__global__ void __launch_bounds__(256) k_big(
    const float* __restrict__ mem, const float* __restrict__ md,
    float* __restrict__ O)
{
    int tid = threadIdx.x, lane = tid & 31, wlocal = tid >> 5;
    float4* O4 = (float4*)O;

    if (blockIdx.x < NB_MEM) {
        // ================= memory stream =================
        __shared__ float enc_s[OUT_DIM];
        __shared__ float bmin[8];
        enc_s[tid]       = g_enc[tid];
        enc_s[tid + 256] = g_enc[tid + 256];
        __syncthreads();

        const float4* mem4 = (const float4*)mem;
        const float4* e4p  = (const float4*)enc_s;
        float4 e[4];
#pragma unroll
        for (int j = 0; j < 4; j++) e[j] = e4p[j * 32 + lane];

        int wg = blockIdx.x * 8 + wlocal;                 // 0 .. 32767
        const int RPW = MEM_LEN / (NB_MEM * 8);           // 4 rows per warp
        int base4 = wg * RPW * 128;                       // float4 index of chunk

        float carry = 0.0f;
        if (lane == 0 && wg > 0) carry = __ldg(&mem[(size_t)base4 * 4 - 1]);

        float localmin = __int_as_float(0x7f800000);
        for (int r = 0; r < RPW; r++) {
            int rb = base4 + r * 128;
            float4 v[4];
#pragma unroll
            for (int j = 0; j < 4; j++) v[j] = mem4[rb + j * 32 + lane];

            float d = 0.0f;
#pragma unroll
            for (int j = 0; j < 4; j++) {
                d += fabsf(v[j].x - e[j].x) + fabsf(v[j].y - e[j].y) +
                     fabsf(v[j].z - e[j].z) + fabsf(v[j].w - e[j].w);
                float wprev = __shfl_up_sync(0xffffffffu, v[j].w, 1);
                if (lane == 0) wprev = carry;
                int i4 = rb + j * 32 + lane;
                if (i4 > 0) {
                    O4[i4] = make_float4(wprev, v[j].x, v[j].y, v[j].z);
                } else {                                   // O[0] is the loss slot
                    O[1] = v[j].x; O[2] = v[j].y; O[3] = v[j].z;
                }
                carry = __shfl_sync(0xffffffffu, v[j].w, 31);
            }
#pragma unroll
            for (int o = 16; o; o >>= 1) d += __shfl_xor_sync(0xffffffffu, d, o);
            localmin = fminf(localmin, d);
        }
        // last element of the memory region: carry == mem[last]
        if (wg == NB_MEM * 8 - 1 && lane == 0)
            O[(size_t)MEM_LEN * OUT_DIM] = carry;

        // one atomic per block
        if (lane == 0) bmin[wlocal] = localmin;
        __syncthreads();
        if (tid == 0) {
            float bm = bmin[0];
#pragma unroll
            for (int i = 1; i < 8; i++) bm = fminf(bm, bmin[i]);
            atomicMin(&g_minbits, __float_as_uint(bm));    // dists >= 0
        }
    } else {
        // ================= mem_data stream =================
        const int    N4   = MEM_LEN * (IN_DIM / 4);        // 8388608
        const int    OB4  = MEM_LEN * (OUT_DIM / 4);       // 16777216
        const size_t base = 1ull + (size_t)MEM_LEN * OUT_DIM;

        const float4* md4 = (const float4*)md;
        int wg = (blockIdx.x - NB_MEM) * 8 + wlocal;       // 0 .. 16383
        const int C4 = N4 / (NB_MD * 8);                   // 512 float4 per warp
        int s0 = wg * C4;

        float carry = 0.0f;
        if (lane == 0 && wg > 0) carry = __ldg(&md[(size_t)s0 * 4 - 1]);

        for (int k = 0; k < C4 / 128; k++) {               // 4 iterations
            int ib = s0 + k * 128;
            float4 v[4];
#pragma unroll
            for (int j = 0; j < 4; j++) v[j] = md4[ib + j * 32 + lane];
#pragma unroll
            for (int j = 0; j < 4; j++) {
                float wprev = __shfl_up_sync(0xffffffffu, v[j].w, 1);
                if (lane == 0) wprev = carry;
                int i = ib + j * 32 + lane;
                if (i > 0) {
                    O4[OB4 + i] = make_float4(wprev, v[j].x, v[j].y, v[j].z);
                } else {                  // don't clobber O[base-1] (mem's last elem)
                    O[base] = v[j].x; O[base + 1] = v[j].y; O[base + 2] = v[j].z;
                }
                carry = __shfl_sync(0xffffffffu, v[j].w, 31);
            }
        }
        // last element of the mem_data region
        if (wg == NB_MD * 8 - 1 && lane == 0)
            O[base + 4ull * N4 - 1] = carry;
    }
}

// ---------------------------------------------------------------------------
// Kernel 3: write loss; conditional ring-buffer row overwrite in the OUTPUT.
// ---------------------------------------------------------------------------
__global__ void __launch_bounds__(512) k_final(
    const float* __restrict__ x, const int* __restrict__ count,
    float* __restrict__ O)
{
    int tid = threadIdx.x;
    float loss = __uint_as_float(g_minbits);
    if (tid == 0) O[0] = loss;
    if (loss <= BETA_F) {
        int pos = count[0] % MEM_LEN;
        O[1LL + (long long)pos * OUT_DIM + tid] = g_enc[tid];
        if (tid < IN_DIM)
            O[1LL + (long long)MEM_LEN * OUT_DIM + (long long)pos * IN_DIM + tid] = x[tid];
    }
}

// ---------------------------------------------------------------------------
extern "C" void kernel_launch(void* const* d_in, const int* in_sizes, int n_in,
                              void* d_out, int out_size)
{
    const float* x        = (const float*)d_in[0];
    const float* W_enc    = (const float*)d_in[1];
    const float* b_enc    = (const float*)d_in[2];
    const float* memory   = (const float*)d_in[3];
    const float* mem_data = (const float*)d_in[4];
    const float* mean     = (const float*)d_in[5];
    const float* stdv     = (const float*)d_in[6];
    const int*   count    = (const int*)d_in[n_in - 1];
    float* O = (float*)d_out;

    k_encoder<<<1, 1024>>>(x, W_enc, b_enc, mean, stdv);
    k_big<<<NB_MEM + NB_MD, 256>>>(memory, mem_data, O);
    k_final<<<1, 512>>>(x, count, O);
}

// round 4
// speedup vs baseline: 1.1118x; 1.0558x over previous
#include <cuda_runtime.h>
#include <math.h>

#define IN_DIM   256
#define OUT_DIM  512
#define MEM_LEN  131072
#define BETA_F   1.0f

#define NB_MEM   4096     // blocks for memory stream (512 MB of traffic)
#define NB_MD    2048     // blocks for mem_data stream (256 MB of traffic)
#define KB_ENC   64       // encoder k-split blocks (4 W-rows each)

// scratch (no device allocs allowed -> __device__ globals)
__device__ float        g_partial[KB_ENC * OUT_DIM];
__device__ float        g_enc[OUT_DIM];
__device__ unsigned int g_minbits;

// ---------------------------------------------------------------------------
// Kernel 1a: k-split partial matvec. 64 blocks x 128 threads; block b handles
// W rows [4b, 4b+4) with float4 loads. Also resets global min (replay-safe).
// ---------------------------------------------------------------------------
__global__ void __launch_bounds__(128) k_enc_partial(
    const float* __restrict__ x, const float* __restrict__ W,
    const float* __restrict__ mean, const float* __restrict__ stdv)
{
    __shared__ float xn[4];
    int tid = threadIdx.x;
    int row0 = blockIdx.x * 4;

    if (tid < 4) {
        int k = row0 + tid;
        float s = stdv[k];
        xn[tid] = (s == 0.0f) ? 0.0f : (x[k] - mean[k]) / s;
    }
    if (blockIdx.x == 0 && tid == 0) g_minbits = 0x7F800000u;   // +inf
    __syncthreads();

    const float4* W4 = (const float4*)W;      // row k = 128 float4s
    float4 acc = make_float4(0.f, 0.f, 0.f, 0.f);
#pragma unroll
    for (int r = 0; r < 4; r++) {
        float4 w = W4[(size_t)(row0 + r) * 128 + tid];
        float  s = xn[r];
        acc.x = fmaf(s, w.x, acc.x);
        acc.y = fmaf(s, w.y, acc.y);
        acc.z = fmaf(s, w.z, acc.z);
        acc.w = fmaf(s, w.w, acc.w);
    }
    ((float4*)g_partial)[(size_t)blockIdx.x * 128 + tid] = acc;
}

// ---------------------------------------------------------------------------
// Kernel 1b: combine 64 partial slabs + bias, block log_softmax -> g_enc
// ---------------------------------------------------------------------------
__global__ void __launch_bounds__(512) k_softmax(const float* __restrict__ b_enc)
{
    int tid  = threadIdx.x;
    int lane = tid & 31, warp = tid >> 5;     // 16 warps
    __shared__ float sred[16];

    float logit = b_enc[tid];
#pragma unroll
    for (int b = 0; b < KB_ENC; b++)
        logit += g_partial[b * OUT_DIM + tid];

    // block max
    float m = logit;
#pragma unroll
    for (int o = 16; o; o >>= 1) m = fmaxf(m, __shfl_xor_sync(0xffffffffu, m, o));
    if (lane == 0) sred[warp] = m;
    __syncthreads();
    m = sred[0];
#pragma unroll
    for (int i = 1; i < 16; i++) m = fmaxf(m, sred[i]);
    __syncthreads();

    // block sum of exp
    float e = expf(logit - m);
    float s = e;
#pragma unroll
    for (int o = 16; o; o >>= 1) s += __shfl_xor_sync(0xffffffffu, s, o);
    if (lane == 0) sred[warp] = s;
    __syncthreads();
    s = 0.0f;
#pragma unroll
    for (int i = 0; i < 16; i++) s += sred[i];

    g_enc[tid] = logit - m - logf(s);
}

// ---------------------------------------------------------------------------
// Kernel 2: fused big streamer (unchanged from R2 — at HBM roofline).
//   blocks [0, NB_MEM):      memory -> O (shifted +1) + L1 distance + min
//   blocks [NB_MEM, +NB_MD): mem_data -> O (shifted +1)
// ---------------------------------------------------------------------------
__global__ void __launch_bounds__(256) k_big(
    const float* __restrict__ mem, const float* __restrict__ md,
    float* __restrict__ O)
{
    int tid = threadIdx.x, lane = tid & 31, wlocal = tid >> 5;
    float4* O4 = (float4*)O;

    if (blockIdx.x < NB_MEM) {
        // ================= memory stream =================
        __shared__ float enc_s[OUT_DIM];
        __shared__ float bmin[8];
        enc_s[tid]       = g_enc[tid];
        enc_s[tid + 256] = g_enc[tid + 256];
        __syncthreads();

        const float4* mem4 = (const float4*)mem;
        const float4* e4p  = (const float4*)enc_s;
        float4 e[4];
#pragma unroll
        for (int j = 0; j < 4; j++) e[j] = e4p[j * 32 + lane];

        int wg = blockIdx.x * 8 + wlocal;                 // 0 .. 32767
        const int RPW = MEM_LEN / (NB_MEM * 8);           // 4 rows per warp
        int base4 = wg * RPW * 128;

        float carry = 0.0f;
        if (lane == 0 && wg > 0) carry = __ldg(&mem[(size_t)base4 * 4 - 1]);

        float localmin = __int_as_float(0x7f800000);
        for (int r = 0; r < RPW; r++) {
            int rb = base4 + r * 128;
            float4 v[4];
#pragma unroll
            for (int j = 0; j < 4; j++) v[j] = mem4[rb + j * 32 + lane];

            float d = 0.0f;
#pragma unroll
            for (int j = 0; j < 4; j++) {
                d += fabsf(v[j].x - e[j].x) + fabsf(v[j].y - e[j].y) +
                     fabsf(v[j].z - e[j].z) + fabsf(v[j].w - e[j].w);
                float wprev = __shfl_up_sync(0xffffffffu, v[j].w, 1);
                if (lane == 0) wprev = carry;
                int i4 = rb + j * 32 + lane;
                if (i4 > 0) {
                    O4[i4] = make_float4(wprev, v[j].x, v[j].y, v[j].z);
                } else {                                   // O[0] is the loss slot
                    O[1] = v[j].x; O[2] = v[j].y; O[3] = v[j].z;
                }
                carry = __shfl_sync(0xffffffffu, v[j].w, 31);
            }
#pragma unroll
            for (int o = 16; o; o >>= 1) d += __shfl_xor_sync(0xffffffffu, d, o);
            localmin = fminf(localmin, d);
        }
        if (wg == NB_MEM * 8 - 1 && lane == 0)
            O[(size_t)MEM_LEN * OUT_DIM] = carry;          // last memory element

        if (lane == 0) bmin[wlocal] = localmin;
        __syncthreads();
        if (tid == 0) {
            float bm = bmin[0];
#pragma unroll
            for (int i = 1; i < 8; i++) bm = fminf(bm, bmin[i]);
            atomicMin(&g_minbits, __float_as_uint(bm));    // dists >= 0
        }
    } else {
        // ================= mem_data stream =================
        const int    N4   = MEM_LEN * (IN_DIM / 4);        // 8388608
        const int    OB4  = MEM_LEN * (OUT_DIM / 4);       // 16777216
        const size_t base = 1ull + (size_t)MEM_LEN * OUT_DIM;

        const float4* md4 = (const float4*)md;
        int wg = (blockIdx.x - NB_MEM) * 8 + wlocal;       // 0 .. 16383
        const int C4 = N4 / (NB_MD * 8);                   // 512 float4 per warp
        int s0 = wg * C4;

        float carry = 0.0f;
        if (lane == 0 && wg > 0) carry = __ldg(&md[(size_t)s0 * 4 - 1]);

        for (int k = 0; k < C4 / 128; k++) {               // 4 iterations
            int ib = s0 + k * 128;
            float4 v[4];
#pragma unroll
            for (int j = 0; j < 4; j++) v[j] = md4[ib + j * 32 + lane];
#pragma unroll
            for (int j = 0; j < 4; j++) {
                float wprev = __shfl_up_sync(0xffffffffu, v[j].w, 1);
                if (lane == 0) wprev = carry;
                int i = ib + j * 32 + lane;
                if (i > 0) {
                    O4[OB4 + i] = make_float4(wprev, v[j].x, v[j].y, v[j].z);
                } else {
                    O[base] = v[j].x; O[base + 1] = v[j].y; O[base + 2] = v[j].z;
                }
                carry = __shfl_sync(0xffffffffu, v[j].w, 31);
            }
        }
        if (wg == NB_MD * 8 - 1 && lane == 0)
            O[base + 4ull * N4 - 1] = carry;               // last mem_data element
    }
}

// ---------------------------------------------------------------------------
// Kernel 3: write loss; conditional ring-buffer row overwrite in the OUTPUT.
// ---------------------------------------------------------------------------
__global__ void __launch_bounds__(512) k_final(
    const float* __restrict__ x, const int* __restrict__ count,
    float* __restrict__ O)
{
    int tid = threadIdx.x;
    float loss = __uint_as_float(g_minbits);
    if (tid == 0) O[0] = loss;
    if (loss <= BETA_F) {
        int pos = count[0] % MEM_LEN;
        O[1LL + (long long)pos * OUT_DIM + tid] = g_enc[tid];
        if (tid < IN_DIM)
            O[1LL + (long long)MEM_LEN * OUT_DIM + (long long)pos * IN_DIM + tid] = x[tid];
    }
}

// ---------------------------------------------------------------------------
extern "C" void kernel_launch(void* const* d_in, const int* in_sizes, int n_in,
                              void* d_out, int out_size)
{
    const float* x        = (const float*)d_in[0];
    const float* W_enc    = (const float*)d_in[1];
    const float* b_enc    = (const float*)d_in[2];
    const float* memory   = (const float*)d_in[3];
    const float* mem_data = (const float*)d_in[4];
    const float* mean     = (const float*)d_in[5];
    const float* stdv     = (const float*)d_in[6];
    const int*   count    = (const int*)d_in[n_in - 1];
    float* O = (float*)d_out;

    k_enc_partial<<<KB_ENC, 128>>>(x, W_enc, mean, stdv);
    k_softmax<<<1, 512>>>(b_enc);
    k_big<<<NB_MEM + NB_MD, 256>>>(memory, mem_data, O);
    k_final<<<1, 512>>>(x, count, O);
}

// round 5
// speedup vs baseline: 1.1227x; 1.0098x over previous
#include <cuda_runtime.h>
#include <math.h>

#define IN_DIM   256
#define OUT_DIM  512
#define MEM_LEN  131072
#define BETA_F   1.0f

#define NB_MEM   4096     // memory-stream blocks (512 MB traffic)
#define NB_MD    2048     // mem_data-stream blocks (256 MB traffic)
#define NB_TOTAL (1 + NB_MD + NB_MEM)
#define KB_ENC   64       // encoder k-split blocks (4 W-rows each)

// scratch (no device allocs allowed -> __device__ globals)
__device__ float        g_partial[KB_ENC * OUT_DIM];
__device__ float        g_enc[OUT_DIM];
__device__ unsigned int g_minbits;
__device__ unsigned int g_ready;
__device__ unsigned int g_done;

// ---------------------------------------------------------------------------
// Launch 1: k-split partial matvec (64 blocks x 128 threads, float4 W loads).
// Block 0 also resets all per-launch flags (graph-replay safe: this node is
// stream-ordered before the big node).
// ---------------------------------------------------------------------------
__global__ void __launch_bounds__(128) k_enc_partial(
    const float* __restrict__ x, const float* __restrict__ W,
    const float* __restrict__ mean, const float* __restrict__ stdv)
{
    __shared__ float xn[4];
    int tid = threadIdx.x;
    int row0 = blockIdx.x * 4;

    if (tid < 4) {
        int k = row0 + tid;
        float s = stdv[k];
        xn[tid] = (s == 0.0f) ? 0.0f : (x[k] - mean[k]) / s;
    }
    if (blockIdx.x == 0 && tid == 0) {
        g_minbits = 0x7F800000u;   // +inf
        g_ready   = 0u;
        g_done    = 0u;
    }
    __syncthreads();

    const float4* W4 = (const float4*)W;      // row k = 128 float4s
    float4 acc = make_float4(0.f, 0.f, 0.f, 0.f);
#pragma unroll
    for (int r = 0; r < 4; r++) {
        float4 w = W4[(size_t)(row0 + r) * 128 + tid];
        float  s = xn[r];
        acc.x = fmaf(s, w.x, acc.x);
        acc.y = fmaf(s, w.y, acc.y);
        acc.z = fmaf(s, w.z, acc.z);
        acc.w = fmaf(s, w.w, acc.w);
    }
    ((float4*)g_partial)[(size_t)blockIdx.x * 128 + tid] = acc;
}

// ---------------------------------------------------------------------------
// Launch 2: everything else, one kernel.
//   block 0:                       softmax (combine partials) -> g_enc, g_ready=1
//   blocks [1, NB_MD]:             mem_data -> O (shifted +1)   [no enc needed]
//   blocks [NB_MD+1, NB_MD+NB_MEM]: spin(g_ready); memory -> O (shifted +1)
//                                   + L1 distance + block min -> atomicMin
//   last block to finish:          loss write + conditional ring-row overwrite
// ---------------------------------------------------------------------------
__global__ void __launch_bounds__(256) k_big(
    const float* __restrict__ mem, const float* __restrict__ md,
    const float* __restrict__ b_enc, const float* __restrict__ x,
    const int* __restrict__ count, float* __restrict__ O)
{
    int tid = threadIdx.x, lane = tid & 31, wlocal = tid >> 5;
    float4* O4 = (float4*)O;
    __shared__ float  sred[8];
    __shared__ float  enc_s[OUT_DIM];
    __shared__ float  bmin[8];
    __shared__ unsigned int s_islast;

    if (blockIdx.x == 0) {
        // ================= softmax (2 logits per thread) =================
        float l0 = b_enc[tid], l1 = b_enc[tid + 256];
#pragma unroll
        for (int b = 0; b < KB_ENC; b++) {
            l0 += g_partial[b * OUT_DIM + tid];
            l1 += g_partial[b * OUT_DIM + tid + 256];
        }
        // block max
        float m = fmaxf(l0, l1);
#pragma unroll
        for (int o = 16; o; o >>= 1) m = fmaxf(m, __shfl_xor_sync(0xffffffffu, m, o));
        if (lane == 0) sred[wlocal] = m;
        __syncthreads();
        m = sred[0];
#pragma unroll
        for (int i = 1; i < 8; i++) m = fmaxf(m, sred[i]);
        __syncthreads();
        // block sum of exp
        float s = expf(l0 - m) + expf(l1 - m);
#pragma unroll
        for (int o = 16; o; o >>= 1) s += __shfl_xor_sync(0xffffffffu, s, o);
        if (lane == 0) sred[wlocal] = s;
        __syncthreads();
        s = 0.0f;
#pragma unroll
        for (int i = 0; i < 8; i++) s += sred[i];
        float ls = logf(s);
        g_enc[tid]       = l0 - m - ls;
        g_enc[tid + 256] = l1 - m - ls;
        __threadfence();
        __syncthreads();
        if (tid == 0) {
            unsigned int one = 1u;
            asm volatile("st.release.gpu.global.u32 [%0], %1;"
                         :: "l"(&g_ready), "r"(one) : "memory");
        }
    } else if (blockIdx.x <= NB_MD) {
        // ================= mem_data stream (no enc dependency) =================
        const int    N4   = MEM_LEN * (IN_DIM / 4);        // 8388608
        const int    OB4  = MEM_LEN * (OUT_DIM / 4);       // 16777216
        const size_t base = 1ull + (size_t)MEM_LEN * OUT_DIM;

        const float4* md4 = (const float4*)md;
        int wg = (blockIdx.x - 1) * 8 + wlocal;            // 0 .. 16383
        const int C4 = N4 / (NB_MD * 8);                   // 512 float4 per warp
        int s0 = wg * C4;

        float carry = 0.0f;
        if (lane == 0 && wg > 0) carry = __ldg(&md[(size_t)s0 * 4 - 1]);

        for (int k = 0; k < C4 / 128; k++) {               // 4 iterations
            int ib = s0 + k * 128;
            float4 v[4];
#pragma unroll
            for (int j = 0; j < 4; j++) v[j] = md4[ib + j * 32 + lane];
#pragma unroll
            for (int j = 0; j < 4; j++) {
                float wprev = __shfl_up_sync(0xffffffffu, v[j].w, 1);
                if (lane == 0) wprev = carry;
                int i = ib + j * 32 + lane;
                if (i > 0) {
                    O4[OB4 + i] = make_float4(wprev, v[j].x, v[j].y, v[j].z);
                } else {
                    O[base] = v[j].x; O[base + 1] = v[j].y; O[base + 2] = v[j].z;
                }
                carry = __shfl_sync(0xffffffffu, v[j].w, 31);
            }
        }
        if (wg == NB_MD * 8 - 1 && lane == 0)
            O[base + 4ull * N4 - 1] = carry;               // last mem_data element
    } else {
        // ================= memory stream =================
        // wait for encoder (block 0); usually already set by the time we start
        if (tid == 0) {
            unsigned int r;
            while (true) {
                asm volatile("ld.acquire.gpu.global.u32 %0, [%1];"
                             : "=r"(r) : "l"(&g_ready) : "memory");
                if (r) break;
                __nanosleep(64);
            }
        }
        __syncthreads();

        enc_s[tid]       = g_enc[tid];
        enc_s[tid + 256] = g_enc[tid + 256];
        __syncthreads();

        const float4* mem4 = (const float4*)mem;
        const float4* e4p  = (const float4*)enc_s;
        float4 e[4];
#pragma unroll
        for (int j = 0; j < 4; j++) e[j] = e4p[j * 32 + lane];

        int wg = (blockIdx.x - 1 - NB_MD) * 8 + wlocal;    // 0 .. 32767
        const int RPW = MEM_LEN / (NB_MEM * 8);            // 4 rows per warp
        int base4 = wg * RPW * 128;

        float carry = 0.0f;
        if (lane == 0 && wg > 0) carry = __ldg(&mem[(size_t)base4 * 4 - 1]);

        float localmin = __int_as_float(0x7f800000);
        for (int r = 0; r < RPW; r++) {
            int rb = base4 + r * 128;
            float4 v[4];
#pragma unroll
            for (int j = 0; j < 4; j++) v[j] = mem4[rb + j * 32 + lane];

            float d = 0.0f;
#pragma unroll
            for (int j = 0; j < 4; j++) {
                d += fabsf(v[j].x - e[j].x) + fabsf(v[j].y - e[j].y) +
                     fabsf(v[j].z - e[j].z) + fabsf(v[j].w - e[j].w);
                float wprev = __shfl_up_sync(0xffffffffu, v[j].w, 1);
                if (lane == 0) wprev = carry;
                int i4 = rb + j * 32 + lane;
                if (i4 > 0) {
                    O4[i4] = make_float4(wprev, v[j].x, v[j].y, v[j].z);
                } else {                                    // O[0] is the loss slot
                    O[1] = v[j].x; O[2] = v[j].y; O[3] = v[j].z;
                }
                carry = __shfl_sync(0xffffffffu, v[j].w, 31);
            }
#pragma unroll
            for (int o = 16; o; o >>= 1) d += __shfl_xor_sync(0xffffffffu, d, o);
            localmin = fminf(localmin, d);
        }
        if (wg == NB_MEM * 8 - 1 && lane == 0)
            O[(size_t)MEM_LEN * OUT_DIM] = carry;           // last memory element

        if (lane == 0) bmin[wlocal] = localmin;
        __syncthreads();
        if (tid == 0) {
            float bm = bmin[0];
#pragma unroll
            for (int i = 1; i < 8; i++) bm = fminf(bm, bmin[i]);
            atomicMin(&g_minbits, __float_as_uint(bm));     // dists >= 0
        }
    }

    // ================= last-block epilogue (was k_final) =================
    __threadfence();
    __syncthreads();
    if (tid == 0) {
        unsigned int old = atomicAdd(&g_done, 1u);
        s_islast = (old == (unsigned)(NB_TOTAL - 1)) ? 1u : 0u;
    }
    __syncthreads();
    if (s_islast) {
        float loss = __uint_as_float(g_minbits);
        if (tid == 0) O[0] = loss;
        if (loss <= BETA_F) {
            int pos = count[0] % MEM_LEN;
            float* Om = O + 1LL + (long long)pos * OUT_DIM;
            Om[tid]       = g_enc[tid];
            Om[tid + 256] = g_enc[tid + 256];
            O[1LL + (long long)MEM_LEN * OUT_DIM + (long long)pos * IN_DIM + tid] = x[tid];
        }
    }
}

// ---------------------------------------------------------------------------
extern "C" void kernel_launch(void* const* d_in, const int* in_sizes, int n_in,
                              void* d_out, int out_size)
{
    const float* x        = (const float*)d_in[0];
    const float* W_enc    = (const float*)d_in[1];
    const float* b_enc    = (const float*)d_in[2];
    const float* memory   = (const float*)d_in[3];
    const float* mem_data = (const float*)d_in[4];
    const float* mean     = (const float*)d_in[5];
    const float* stdv     = (const float*)d_in[6];
    const int*   count    = (const int*)d_in[n_in - 1];
    float* O = (float*)d_out;

    k_enc_partial<<<KB_ENC, 128>>>(x, W_enc, mean, stdv);
    k_big<<<NB_TOTAL, 256>>>(memory, mem_data, b_enc, x, count, O);
}